// round 12
// baseline (speedup 1.0000x reference)
#include <cuda_runtime.h>
#include <cstdint>

// Problem constants (fixed by setup_inputs)
#define N      2048
#define DMDIM  128
#define KDIAG  (2*N - 1)           // 4095 anti-diagonals
#define DIAG_ELEMS (KDIAG * N)     // 8,386,560
#define BIGF   1e10f
#define GAMMA_ 0.1f
#define INVG   10.0f               // 1/GAMMA
#define MARGINF 2.0f

#define CSPLIT 16                  // CTAs per matrix in the wavefront
#define BCOLS  128                 // columns per CTA
#define CPL    4                   // columns per lane
#define TSTEP  64                  // steps per tile (flag granularity)
#define NTILES 64                  // 64*64 = 4096 >= KDIAG

// Static scratch only (no runtime allocation allowed)
__device__ float  g_D[3][DIAG_ELEMS];        // diag-major: D[z][(i+j)*N + i]
__device__ float  g_norms[2][N];
__device__ float  g_dtw[3];
__device__ double g_part[512];
__device__ __align__(16) float2 g_rec[3][CSPLIT][KDIAG + 1]; // (r1,r2) per step
__device__ volatile int g_flag[3][CSPLIT];   // tiles completed per (m, c)

// ---------------------------------------------------------------------------
// Kernel A: clear tile flags (per launch/replay)
// ---------------------------------------------------------------------------
__global__ void clear_flags_kernel() {
    int i = threadIdx.x;
    if (i < 3 * CSPLIT) g_flag[i / CSPLIT][i % CSPLIT] = 0;
}

// ---------------------------------------------------------------------------
// Kernel 0: row squared norms for x and y
// ---------------------------------------------------------------------------
__global__ void norm_kernel(const float* __restrict__ x,
                            const float* __restrict__ y) {
    int r = blockIdx.x * blockDim.x + threadIdx.x;   // 0..2N-1
    if (r >= 2 * N) return;
    const float* p = (r < N) ? (x + (size_t)r * DMDIM)
                             : (y + (size_t)(r - N) * DMDIM);
    const float4* p4 = (const float4*)p;
    float s = 0.0f;
#pragma unroll
    for (int k = 0; k < DMDIM / 4; k++) {
        float4 v = p4[k];
        s += v.x * v.x + v.y * v.y + v.z * v.z + v.w * v.w;
    }
    g_norms[r < N ? 0 : 1][r < N ? r : r - N] = s;
}

// ---------------------------------------------------------------------------
// Kernel 1: pairwise sqdist -> diag-major (smem-staged, coalesced writeout),
// fused contrastive-IDM reduction for z=1 (x,x) and z=2 (y,y).
// ---------------------------------------------------------------------------
#define TILE 128
#define KC   16
#define DS_STRIDE 130

extern __shared__ float sdyn[];  // Ds[128][130] = 66560 B

__global__ __launch_bounds__(256)
void pairdist_kernel(const float* __restrict__ x,
                     const float* __restrict__ y,
                     const float* __restrict__ aidx,
                     const float* __restrict__ bidx,
                     float thr) {
    int z = blockIdx.z;
    const float* A  = (z == 2) ? y : x;
    const float* B  = (z == 1) ? x : y;
    const float* nA = (z == 2) ? g_norms[1] : g_norms[0];
    const float* nB = (z == 1) ? g_norms[0] : g_norms[1];
    const float* gidx = (z == 1) ? aidx : bidx;

    int bi = blockIdx.y, bj = blockIdx.x;
    __shared__ float As[TILE][KC + 1];
    __shared__ float Bs[TILE][KC + 1];
    __shared__ double sh[256];

    int t  = threadIdx.x;
    int tx = t & 15, ty = t >> 4;

    float acc[8][8];
#pragma unroll
    for (int u = 0; u < 8; u++)
#pragma unroll
        for (int v = 0; v < 8; v++) acc[u][v] = 0.0f;

    for (int kb = 0; kb < DMDIM; kb += KC) {
        for (int idx = t; idx < TILE * KC; idx += 256) {
            int rr = idx >> 4, kk = idx & 15;
            As[rr][kk] = A[(size_t)(bi * TILE + rr) * DMDIM + kb + kk];
            Bs[rr][kk] = B[(size_t)(bj * TILE + rr) * DMDIM + kb + kk];
        }
        __syncthreads();
#pragma unroll
        for (int kk = 0; kk < KC; kk++) {
            float a[8], b[8];
#pragma unroll
            for (int u = 0; u < 8; u++) a[u] = As[ty + 16 * u][kk];
#pragma unroll
            for (int v = 0; v < 8; v++) b[v] = Bs[tx + 16 * v][kk];
#pragma unroll
            for (int u = 0; u < 8; u++)
#pragma unroll
                for (int v = 0; v < 8; v++) acc[u][v] += a[u] * b[v];
        }
        __syncthreads();
    }

    float gxu[8], gxv[8], nau[8], nbv[8];
#pragma unroll
    for (int u = 0; u < 8; u++) {
        int gi = bi * TILE + ty + 16 * u;
        nau[u] = nA[gi];
        gxu[u] = (z != 0) ? gidx[gi] : 0.0f;
    }
#pragma unroll
    for (int v = 0; v < 8; v++) {
        int gj = bj * TILE + tx + 16 * v;
        nbv[v] = nB[gj];
        gxv[v] = (z != 0) ? gidx[gj] : 0.0f;
    }

    float idm_acc = 0.0f;
#pragma unroll
    for (int u = 0; u < 8; u++) {
        int li = ty + 16 * u;
#pragma unroll
        for (int v = 0; v < 8; v++) {
            int lj = tx + 16 * v;
            float d = fmaxf(nau[u] + nbv[v] - 2.0f * acc[u][v], 0.0f);
            sdyn[li * DS_STRIDE + lj] = d;
            if (z != 0) {
                float gd   = gxu[u] - gxv[v];
                float prob = fmaxf(MARGINF - d, 0.0f);
                idm_acc += ((fabsf(gd) - thr) > 0.0f)
                             ? (1.0f + gd * gd) * prob : d;
            }
        }
    }
    __syncthreads();

    float* Dz = g_D[z];
    int kbase = (bi + bj) * TILE;
    int half  = t >> 7;
    int tt    = t & 127;
    for (int kp = 0; kp < 255; kp += 2) {
        int k1 = kp + half;
        if (k1 < 255) {
            int ilo = max(0, k1 - 127), ihi = min(127, k1);
            int i = ilo + tt;
            if (i <= ihi)
                Dz[(size_t)(kbase + k1) * N + bi * TILE + i] =
                    sdyn[i * DS_STRIDE + (k1 - i)];
        }
    }

    if (z != 0) {
        sh[t] = (double)idm_acc;
        __syncthreads();
        for (int off = 128; off > 0; off >>= 1) {
            if (t < off) sh[t] += sh[t + off];
            __syncthreads();
        }
        if (t == 0)
            g_part[(z - 1) * 256 + bi * 16 + bj] = sh[0];
    }
}

// ---------------------------------------------------------------------------
// softmin cell:  out = d + softmin(left, up, diag)
// Exact skip: both margins <= -2 => e1+e2 < 2^-24 => 1+e1+e2 == 1.0f exactly.
// ---------------------------------------------------------------------------
__device__ __forceinline__ float cellf(float d, float left, float up,
                                       float dg, bool valid) {
    float lo = fminf(dg, up), hi = fmaxf(dg, up);
    float mm = fminf(lo, left);
    float o1 = fmaxf(lo, left);
    float o2 = hi;
    float m1 = mm - o1, m2 = mm - o2;        // both <= 0
    float smin;
    if (fmaxf(m1, m2) > -2.0f) {
        float e1 = __expf(m1 * INVG);
        float e2 = __expf(m2 * INVG);
        smin = mm - GAMMA_ * __logf(1.0f + e1 + e2);
    } else {
        smin = mm;
    }
    return valid ? (d + smin) : BIGF;
}

// ---------------------------------------------------------------------------
// Kernel 2: skew-tiled multi-CTA soft-DTW wavefront.
// 3 matrices x 16 one-warp CTAs, 4 columns/lane. Cross-CTA boundary records
// exchanged in tiles of TSTEP steps via bulk stores + threadfence + a
// monotonic flag; per-step boundary access is a broadcast LDS only.
// ---------------------------------------------------------------------------
__global__ __launch_bounds__(32)
void softdtw_kernel() {
    const int bid  = blockIdx.x;
    const int m    = bid / CSPLIT;
    const int c    = bid % CSPLIT;
    const int lane = threadIdx.x;
    const float* base = g_D[m];
    const int col0 = c * BCOLS + lane * CPL;

    __shared__ __align__(16) float2 s_rec[TSTEP];   // neighbor records (step k-1)
    __shared__ __align__(16) float2 s_save[TSTEP];  // our boundary records

    const int t0 = (c * BCOLS) / TSTEP;             // 2c
    const int t1 = min(NTILES - 1, (c * BCOLS + BCOLS - 1 + N - 1) / TSTEP);
    const bool has_left  = (c > 0);
    const bool has_right = (c < CSPLIT - 1);
    const bool is_last   = (c == CSPLIT - 1);
    int prod_t1 = 0;
    if (has_left)
        prod_t1 = min(NTILES - 1,
                      ((c - 1) * BCOLS + BCOLS - 1 + N - 1) / TSTEP);

    float r1[CPL], r2[CPL];
#pragma unroll
    for (int q = 0; q < CPL; q++) { r1[q] = BIGF; r2[q] = BIGF; }
    if (c == 0 && lane == 0) r1[0] = base[0];       // state after step k=0
    float n1_prev = BIGF;                           // carry: diag(k) = up(k-1)

    if (!has_left) {                                // c==0: boundary is BIG forever
        s_rec[lane]      = make_float2(BIGF, BIGF);
        s_rec[lane + 32] = make_float2(BIGF, BIGF);
    }

    // D-row register ring, rows kstart..kstart+7 (kstart tile-aligned, %8==0)
    const int kstart = t0 * TSTEP;
    float4 ring[8];
#pragma unroll
    for (int q = 0; q < 8; q++)
        ring[q] = *(const float4*)(base + (size_t)(kstart + q) * N + col0);

    for (int t = t0; t <= t1; t++) {
        const int kbase = t * TSTEP;

        if (has_left) {
            // tile t needs records for steps [kbase-1, kbase+TSTEP-2],
            // all produced by neighbor tiles <= t  ->  wait flag >= t+1
            // (capped by neighbor's final flag; excess slots feed invalid cells)
            int want = min(t, prod_t1) + 1;
            if (lane == 0) {
                while (g_flag[m][c - 1] < want) { }
            }
            __syncwarp();
            __threadfence();
            int sbase = kbase - 1 + lane * 2;
            float2 a = __ldcg(&g_rec[m][c - 1][sbase]);
            float2 b = __ldcg(&g_rec[m][c - 1][sbase + 1]);
            s_rec[lane * 2]     = a;
            s_rec[lane * 2 + 1] = b;
        }
        __syncwarp();

#pragma unroll 8
        for (int j = 0; j < TSTEP; j++) {
            const int k = kbase + j;
            float4 d4 = ring[k & 7];
            int nk = k + 8;
            if (nk < KDIAG)
                ring[k & 7] = *(const float4*)(base + (size_t)nk * N + col0);

            if (k != 0) {      // k==0 is the initial state, not a recurrence step
                float nsh = __shfl_up_sync(0xffffffffu, r1[CPL - 1], 1);
                float2 rc = s_rec[j];          // broadcast LDS
                float n1 = (lane == 0) ? rc.x : nsh;
                float n2 = (lane == 0) ? rc.y : n1_prev;
                n1_prev = nsh;

                int rel = k - col0;
                bool v0 = (unsigned)rel       < (unsigned)N;
                bool v1 = (unsigned)(rel - 1) < (unsigned)N;
                bool v2 = (unsigned)(rel - 2) < (unsigned)N;
                bool v3 = (unsigned)(rel - 3) < (unsigned)N;

                float o0 = cellf(d4.x, r1[0], n1,    n2,    v0);
                float o1 = cellf(d4.y, r1[1], r1[0], r2[0], v1);
                float o2 = cellf(d4.z, r1[2], r1[1], r2[1], v2);
                float o3 = cellf(d4.w, r1[3], r1[2], r2[2], v3);
                r2[0] = r1[0]; r2[1] = r1[1]; r2[2] = r1[2]; r2[3] = r1[3];
                r1[0] = o0;    r1[1] = o1;    r1[2] = o2;    r1[3] = o3;

                if (lane == 31) {
                    s_save[j] = make_float2(o3, r2[CPL - 1]); // (r1_k, r2_k)
                    if (is_last && k == KDIAG - 1) g_dtw[m] = o3;
                }
            }
        }

        if (has_right) {
            __syncwarp();      // lane31's s_save visible to all lanes
            float4 w = *(const float4*)&s_save[lane * 2];
            *(float4*)&g_rec[m][c][kbase + lane * 2] = w;
            __threadfence();   // each lane orders its own stores
            __syncwarp();
            if (lane == 0) g_flag[m][c] = t + 1;   // release flag
        }
    }
}

// ---------------------------------------------------------------------------
// Kernel 3: combine -> scalar output
// ---------------------------------------------------------------------------
__global__ __launch_bounds__(256)
void combine_kernel(float* __restrict__ out) {
    __shared__ double sh[256];
    double s = 0.0;
    for (int i = threadIdx.x; i < 512; i += 256) s += g_part[i];
    sh[threadIdx.x] = s;
    __syncthreads();
    for (int off = 128; off > 0; off >>= 1) {
        if (threadIdx.x < off) sh[threadIdx.x] += sh[threadIdx.x + off];
        __syncthreads();
    }
    if (threadIdx.x == 0) {
        double pos = (double)g_dtw[0] - 0.5 * ((double)g_dtw[1] + (double)g_dtw[2]);
        out[0] = (float)((pos + sh[0]) * (1.0 / 2048.0));   // / NUM_FRAMES
    }
}

// ---------------------------------------------------------------------------
extern "C" void kernel_launch(void* const* d_in, const int* in_sizes, int n_in,
                              void* d_out, int out_size) {
    const float* a_emb = (const float*)d_in[0];
    const float* b_emb = (const float*)d_in[1];
    const float* a_idx = (const float*)d_in[2];
    const float* b_idx = (const float*)d_in[3];
    int n = in_sizes[2];                       // 2048
    float thr = 10.0f / (float)n;              // SIGMA / seq_len (exact dyadic)

    cudaFuncSetAttribute(pairdist_kernel,
                         cudaFuncAttributeMaxDynamicSharedMemorySize,
                         TILE * DS_STRIDE * (int)sizeof(float));

    clear_flags_kernel<<<1, 64>>>();
    norm_kernel<<<(2 * N + 255) / 256, 256>>>(a_emb, b_emb);

    dim3 pg(N / TILE, N / TILE, 3);
    pairdist_kernel<<<pg, 256, TILE * DS_STRIDE * sizeof(float)>>>(
        a_emb, b_emb, a_idx, b_idx, thr);

    softdtw_kernel<<<3 * CSPLIT, 32>>>();

    combine_kernel<<<1, 256>>>((float*)d_out);
}

// round 14
// speedup vs baseline: 1.9749x; 1.9749x over previous
#include <cuda_runtime.h>
#include <cstdint>

// Problem constants (fixed by setup_inputs)
#define N      2048
#define DMDIM  128
#define KDIAG  (2*N - 1)           // 4095 anti-diagonals
#define DIAG_ELEMS (KDIAG * N)     // 8,386,560
#define BIGF   1e10f
#define GAMMA_ 0.1f
#define INVG   10.0f               // 1/GAMMA
#define MARGINF 2.0f

// Static scratch only (no runtime allocation allowed)
__device__ float  g_D[3][DIAG_ELEMS];        // diag-major: D[z][(i+j)*N + i]
__device__ float  g_norms[2][N];
__device__ float  g_dtw[3];
__device__ double g_part[512];

// ---------------------------------------------------------------------------
// Kernel 0: row squared norms for x and y
// ---------------------------------------------------------------------------
__global__ void norm_kernel(const float* __restrict__ x,
                            const float* __restrict__ y) {
    int r = blockIdx.x * blockDim.x + threadIdx.x;   // 0..2N-1
    if (r >= 2 * N) return;
    const float* p = (r < N) ? (x + (size_t)r * DMDIM)
                             : (y + (size_t)(r - N) * DMDIM);
    const float4* p4 = (const float4*)p;
    float s = 0.0f;
#pragma unroll
    for (int k = 0; k < DMDIM / 4; k++) {
        float4 v = p4[k];
        s += v.x * v.x + v.y * v.y + v.z * v.z + v.w * v.w;
    }
    g_norms[r < N ? 0 : 1][r < N ? r : r - N] = s;
}

// ---------------------------------------------------------------------------
// Kernel 1: pairwise sqdist -> diag-major (smem-staged, coalesced writeout),
// fused contrastive-IDM reduction for z=1 (x,x) and z=2 (y,y).
// (validated passing in R12)
// ---------------------------------------------------------------------------
#define TILE 128
#define KC   16
#define DS_STRIDE 130

extern __shared__ float sdyn[];  // Ds[128][130] = 66560 B

__global__ __launch_bounds__(256)
void pairdist_kernel(const float* __restrict__ x,
                     const float* __restrict__ y,
                     const float* __restrict__ aidx,
                     const float* __restrict__ bidx,
                     float thr) {
    int z = blockIdx.z;
    const float* A  = (z == 2) ? y : x;
    const float* B  = (z == 1) ? x : y;
    const float* nA = (z == 2) ? g_norms[1] : g_norms[0];
    const float* nB = (z == 1) ? g_norms[0] : g_norms[1];
    const float* gidx = (z == 1) ? aidx : bidx;

    int bi = blockIdx.y, bj = blockIdx.x;
    __shared__ float As[TILE][KC + 1];
    __shared__ float Bs[TILE][KC + 1];
    __shared__ double sh[256];

    int t  = threadIdx.x;
    int tx = t & 15, ty = t >> 4;

    float acc[8][8];
#pragma unroll
    for (int u = 0; u < 8; u++)
#pragma unroll
        for (int v = 0; v < 8; v++) acc[u][v] = 0.0f;

    for (int kb = 0; kb < DMDIM; kb += KC) {
        for (int idx = t; idx < TILE * KC; idx += 256) {
            int rr = idx >> 4, kk = idx & 15;
            As[rr][kk] = A[(size_t)(bi * TILE + rr) * DMDIM + kb + kk];
            Bs[rr][kk] = B[(size_t)(bj * TILE + rr) * DMDIM + kb + kk];
        }
        __syncthreads();
#pragma unroll
        for (int kk = 0; kk < KC; kk++) {
            float a[8], b[8];
#pragma unroll
            for (int u = 0; u < 8; u++) a[u] = As[ty + 16 * u][kk];
#pragma unroll
            for (int v = 0; v < 8; v++) b[v] = Bs[tx + 16 * v][kk];
#pragma unroll
            for (int u = 0; u < 8; u++)
#pragma unroll
                for (int v = 0; v < 8; v++) acc[u][v] += a[u] * b[v];
        }
        __syncthreads();
    }

    float gxu[8], gxv[8], nau[8], nbv[8];
#pragma unroll
    for (int u = 0; u < 8; u++) {
        int gi = bi * TILE + ty + 16 * u;
        nau[u] = nA[gi];
        gxu[u] = (z != 0) ? gidx[gi] : 0.0f;
    }
#pragma unroll
    for (int v = 0; v < 8; v++) {
        int gj = bj * TILE + tx + 16 * v;
        nbv[v] = nB[gj];
        gxv[v] = (z != 0) ? gidx[gj] : 0.0f;
    }

    float idm_acc = 0.0f;
#pragma unroll
    for (int u = 0; u < 8; u++) {
        int li = ty + 16 * u;
#pragma unroll
        for (int v = 0; v < 8; v++) {
            int lj = tx + 16 * v;
            float d = fmaxf(nau[u] + nbv[v] - 2.0f * acc[u][v], 0.0f);
            sdyn[li * DS_STRIDE + lj] = d;
            if (z != 0) {
                float gd   = gxu[u] - gxv[v];
                float prob = fmaxf(MARGINF - d, 0.0f);
                idm_acc += ((fabsf(gd) - thr) > 0.0f)
                             ? (1.0f + gd * gd) * prob : d;
            }
        }
    }
    __syncthreads();

    float* Dz = g_D[z];
    int kbase = (bi + bj) * TILE;
    int half  = t >> 7;
    int tt    = t & 127;
    for (int kp = 0; kp < 255; kp += 2) {
        int k1 = kp + half;
        if (k1 < 255) {
            int ilo = max(0, k1 - 127), ihi = min(127, k1);
            int i = ilo + tt;
            if (i <= ihi)
                Dz[(size_t)(kbase + k1) * N + bi * TILE + i] =
                    sdyn[i * DS_STRIDE + (k1 - i)];
        }
    }

    if (z != 0) {
        sh[t] = (double)idm_acc;
        __syncthreads();
        for (int off = 128; off > 0; off >>= 1) {
            if (t < off) sh[t] += sh[t + off];
            __syncthreads();
        }
        if (t == 0)
            g_part[(z - 1) * 256 + bi * 16 + bj] = sh[0];
    }
}

// ---------------------------------------------------------------------------
// softmin cell:  out = d + softmin(left, up, diag)
// Exact skip: both margins <= -2 => e1+e2 < 2^-24 => 1+e1+e2 == 1.0f exactly.
// ---------------------------------------------------------------------------
__device__ __forceinline__ float cellf(float d, float left, float up,
                                       float dg, bool valid) {
    float lo = fminf(dg, up), hi = fmaxf(dg, up);
    float mm = fminf(lo, left);
    float o1 = fmaxf(lo, left);
    float o2 = hi;
    float m1 = mm - o1, m2 = mm - o2;        // both <= 0
    float smin;
    if (fmaxf(m1, m2) > -2.0f) {
        float e1 = __expf(m1 * INVG);
        float e2 = __expf(m2 * INVG);
        smin = mm - GAMMA_ * __logf(1.0f + e1 + e2);
    } else {
        smin = mm;
    }
    return valid ? (d + smin) : BIGF;
}

// ---------------------------------------------------------------------------
// Kernel 2: soft-DTW anti-diagonal wavefront — R2-proven architecture
// (one 1024-thread CTA per matrix, smem ping-pong, one barrier per step)
// + per-warp-half band clipping: a warp computes a 32-column half only while
// the anti-diagonal intersects [w32, w32+31+N-1]. Outside that window the
// slots are init-BIGF (pre-band; readers need BIGF) or stale (post-band;
// provably never read by a valid cell — coverage is exactly tight).
// ---------------------------------------------------------------------------
__global__ __launch_bounds__(1024)
void softdtw_kernel() {
    __shared__ float buf[3][N];
    int m = blockIdx.x;
    const float* base = g_D[m];
    int t = threadIdx.x;

    // ALL THREE buffers init to BIG (buf[2] too: band-skip relies on it)
    buf[0][t] = BIGF;  buf[0][t + 1024] = BIGF;
    buf[1][t] = BIGF;  buf[1][t + 1024] = BIGF;
    buf[2][t] = BIGF;  buf[2][t + 1024] = BIGF;
    if (t == 0) buf[1][0] = base[0];     // r1[0] = D[0,0]
    __syncthreads();

    int r2 = 0, r1 = 1, rn = 2;
    const int w32 = t & ~31;             // warp-uniform column base (half A)

    for (int k = 1; k < KDIAG; k++) {
        const float* drow = base + (size_t)k * N;

        // half A: columns [w32, w32+31], i = t
        if (k >= w32 && k <= w32 + 31 + N - 1) {
            int i = t;
            bool valid = (i <= k) && (k - i < N);
            float d    = drow[i];
            float left = buf[r1][i];
            float up   = (i > 0) ? buf[r1][i - 1] : BIGF;
            float dg   = (i > 0) ? buf[r2][i - 1] : BIGF;
            buf[rn][i] = cellf(d, left, up, dg, valid);
        }

        // half B: columns [w32+1024, w32+1055], i = t + 1024  (i-1 >= 1023)
        {
            int wb = w32 + 1024;
            if (k >= wb && k <= wb + 31 + N - 1) {
                int i = t + 1024;
                bool valid = (i <= k) && (k - i < N);
                float d    = drow[i];
                float left = buf[r1][i];
                float up   = buf[r1][i - 1];
                float dg   = buf[r2][i - 1];
                buf[rn][i] = cellf(d, left, up, dg, valid);
            }
        }

        __syncthreads();
        int tmp = r2; r2 = r1; r1 = rn; rn = tmp;
    }
    if (t == 0) g_dtw[m] = buf[r1][N - 1];
}

// ---------------------------------------------------------------------------
// Kernel 3: combine -> scalar output
// ---------------------------------------------------------------------------
__global__ __launch_bounds__(256)
void combine_kernel(float* __restrict__ out) {
    __shared__ double sh[256];
    double s = 0.0;
    for (int i = threadIdx.x; i < 512; i += 256) s += g_part[i];
    sh[threadIdx.x] = s;
    __syncthreads();
    for (int off = 128; off > 0; off >>= 1) {
        if (threadIdx.x < off) sh[threadIdx.x] += sh[threadIdx.x + off];
        __syncthreads();
    }
    if (threadIdx.x == 0) {
        double pos = (double)g_dtw[0] - 0.5 * ((double)g_dtw[1] + (double)g_dtw[2]);
        out[0] = (float)((pos + sh[0]) * (1.0 / 2048.0));   // / NUM_FRAMES
    }
}

// ---------------------------------------------------------------------------
extern "C" void kernel_launch(void* const* d_in, const int* in_sizes, int n_in,
                              void* d_out, int out_size) {
    const float* a_emb = (const float*)d_in[0];
    const float* b_emb = (const float*)d_in[1];
    const float* a_idx = (const float*)d_in[2];
    const float* b_idx = (const float*)d_in[3];
    int n = in_sizes[2];                       // 2048
    float thr = 10.0f / (float)n;              // SIGMA / seq_len (exact dyadic)

    cudaFuncSetAttribute(pairdist_kernel,
                         cudaFuncAttributeMaxDynamicSharedMemorySize,
                         TILE * DS_STRIDE * (int)sizeof(float));

    norm_kernel<<<(2 * N + 255) / 256, 256>>>(a_emb, b_emb);

    dim3 pg(N / TILE, N / TILE, 3);
    pairdist_kernel<<<pg, 256, TILE * DS_STRIDE * sizeof(float)>>>(
        a_emb, b_emb, a_idx, b_idx, thr);

    softdtw_kernel<<<3, 1024>>>();

    combine_kernel<<<1, 256>>>((float*)d_out);
}